// round 1
// baseline (speedup 1.0000x reference)
#include <cuda_runtime.h>

// Problem constants
constexpr int D  = 128;   // D_IN
constexpr int C  = 64;    // NUM_CLASSES
constexpr int E  = 64;    // D_OUT
constexpr int G1 = 148;   // pass-1 grid (one block per SM)
constexpr int TPB1 = 512;
constexpr int GROUPS = 4; // row groups per block (one smem replica each)
constexpr int U = 16;     // rows per group per iteration -> 64 rows/block/iter

// Scratch (allocation-free): per-block partial segment sums and counts
__device__ float g_partS[G1 * C * D];   // ~4.85 MB
__device__ int   g_partCnt[G1 * C];

__global__ __launch_bounds__(TPB1, 1)
void pass1_kernel(const float* __restrict__ x,
                  const int* __restrict__ labels,
                  int n) {
    extern __shared__ float sm[];
    float* acc_all = sm;                              // GROUPS * C * D floats
    int*   scntw   = (int*)(sm + GROUPS * C * D);     // 16 warps * C ints

    const int tid = threadIdx.x;
    const int grp = tid >> 7;      // row-group 0..3
    const int col = tid & 127;     // owned column
    const int wid = tid >> 5;      // warp id 0..15
    float* acc = acc_all + grp * (C * D);

    for (int i = tid; i < GROUPS * C * D; i += TPB1) acc_all[i] = 0.f;
    for (int i = tid; i < 16 * C; i += TPB1) scntw[i] = 0;
    __syncthreads();

    // contiguous chunk per block, multiple of 64 rows (keeps int4 label loads aligned)
    const int chunk = ((n + G1 * 64 - 1) / (G1 * 64)) * 64;
    const int r0 = blockIdx.x * chunk;
    const int r1 = min(n, r0 + chunk);

    int row = r0;
    for (; row + GROUPS * U <= r1; row += GROUPS * U) {
        const int base = row + grp * U;

        // labels: vectorized (base is 16-aligned by construction)
        int lab[U];
        {
            const int4* lp = (const int4*)(labels + base);
            #pragma unroll
            for (int k = 0; k < U / 4; k++) {
                int4 l4 = lp[k];
                lab[4*k+0] = l4.x; lab[4*k+1] = l4.y;
                lab[4*k+2] = l4.z; lab[4*k+3] = l4.w;
            }
        }

        // data: U independent coalesced loads (MLP), all in flight before use
        float v[U];
        #pragma unroll
        for (int u = 0; u < U; u++)
            v[u] = x[(size_t)(base + u) * D + col];

        // non-atomic accumulate: this thread exclusively owns column `col`
        // within its group's replica
        #pragma unroll
        for (int u = 0; u < U; u++)
            acc[lab[u] * D + col] += v[u];

        // counts: lane 0 of each warp serially counts its 4 rows into its
        // private replica (no races, no atomics, constant register indexing)
        #pragma unroll
        for (int w = 0; w < 4; w++) {
            if (col == w * 32) {
                #pragma unroll
                for (int k = 0; k < 4; k++)
                    scntw[wid * C + lab[w * 4 + k]] += 1;
            }
        }
    }

    // tail rows (group 0 only, scalar)
    if (grp == 0) {
        for (int m = row; m < r1; m++) {
            int lb = labels[m];
            acc[lb * D + col] += x[(size_t)m * D + col];
            if (col == 0) scntw[lb] += 1;
        }
    }
    __syncthreads();

    // merge replicas, write block partials (coalesced)
    for (int i = tid; i < C * D; i += TPB1) {
        float s = acc_all[i] + acc_all[C * D + i]
                + acc_all[2 * C * D + i] + acc_all[3 * C * D + i];
        g_partS[(size_t)blockIdx.x * (C * D) + i] = s;
    }
    if (tid < C) {
        int s = 0;
        #pragma unroll
        for (int w = 0; w < 16; w++) s += scntw[w * C + tid];
        g_partCnt[blockIdx.x * C + tid] = s;
    }
}

__global__ __launch_bounds__(256)
void pass2_kernel(const float* __restrict__ W,
                  const float* __restrict__ bias,
                  float* __restrict__ out) {
    __shared__ float Srow[D];
    __shared__ float sW[D * E];     // 32 KB
    __shared__ float sPart[256];
    __shared__ float sCnt;

    const int c   = blockIdx.x;     // class
    const int tid = threadIdx.x;
    const int half = tid >> 7;      // split g-range for 2x MLP
    const int d    = tid & 127;

    // reduce partial sums for this class across pass-1 blocks
    float s = 0.f;
    #pragma unroll 8
    for (int g = half; g < G1; g += 2)
        s += g_partS[(size_t)g * (C * D) + c * D + d];
    sPart[tid] = s;

    // stage W into smem (coalesced)
    for (int i = tid; i < D * E; i += 256) sW[i] = W[i];

    // reduce counts (warp 0)
    if (tid < 32) {
        int cs = 0;
        for (int g = tid; g < G1; g += 32) cs += g_partCnt[g * C + c];
        #pragma unroll
        for (int o = 16; o; o >>= 1) cs += __shfl_down_sync(0xffffffffu, cs, o);
        if (tid == 0) sCnt = (float)cs;
    }
    __syncthreads();

    if (half == 0) Srow[d] = sPart[d] + sPart[128 + d];
    __syncthreads();

    // protos[c][e] = (S[c] . W[:,e] + cnt*b[e]) / max(cnt,1)
    if (tid < E) {
        float acc = 0.f;
        #pragma unroll
        for (int dd = 0; dd < D; dd++)
            acc += Srow[dd] * sW[dd * E + tid];
        float cnt = sCnt;
        out[c * E + tid] = (acc + cnt * bias[tid]) / fmaxf(cnt, 1.f);
    }
}

extern "C" void kernel_launch(void* const* d_in, const int* in_sizes, int n_in,
                              void* d_out, int out_size) {
    const float* x      = (const float*)d_in[0];   // [N, 128] f32
    const int*   labels = (const int*)d_in[1];     // [N] i32
    const float* W      = (const float*)d_in[2];   // [128, 64] f32
    const float* bias   = (const float*)d_in[3];   // [64] f32
    float* out = (float*)d_out;                    // [64, 64] f32

    const int n = in_sizes[1];                     // N from labels

    const size_t smem1 = (size_t)GROUPS * C * D * sizeof(float)
                       + 16 * C * sizeof(int);     // 135,168 B
    cudaFuncSetAttribute(pass1_kernel,
                         cudaFuncAttributeMaxDynamicSharedMemorySize,
                         (int)smem1);

    pass1_kernel<<<G1, TPB1, smem1>>>(x, labels, n);
    pass2_kernel<<<C, 256>>>(W, bias, out);
}

// round 2
// speedup vs baseline: 1.4151x; 1.4151x over previous
#include <cuda_runtime.h>

constexpr int D  = 128;   // D_IN
constexpr int C  = 64;    // NUM_CLASSES
constexpr int E  = 64;    // D_OUT
constexpr int G1 = 148;   // pass-1 grid (one block per SM)
constexpr int TPB1 = 384; // 12 warps
constexpr int GROUPS = 6; // 2 warps per group, one 32KB replica each
constexpr int U = 16;     // rows per group per iteration
constexpr int ROWS_ITER = GROUPS * U;  // 96 rows / block / iter

// Scratch (allocation-free). Layout: [C][G1][D] so pass2 reads contiguously.
__device__ float g_partS[(size_t)C * G1 * D];   // ~4.85 MB
__device__ int   g_partCnt[G1 * C];

__global__ __launch_bounds__(TPB1, 1)
void pass1_kernel(const float* __restrict__ x,
                  const int* __restrict__ labels,
                  int n) {
    extern __shared__ float sm[];
    float* acc_all = sm;                               // GROUPS * C * D
    int*   scntw   = (int*)(sm + GROUPS * C * D);      // 12 warps * C

    const int tid  = threadIdx.x;
    const int grp  = tid >> 6;        // group 0..5 (2 warps each)
    const int ltid = tid & 63;        // lane within group
    const int wid  = tid >> 5;        // warp id 0..11
    const int col2 = ltid * 2;        // owned column pair
    float* acc = acc_all + grp * (C * D);

    for (int i = tid; i < GROUPS * C * D; i += TPB1) acc_all[i] = 0.f;
    for (int i = tid; i < 12 * C; i += TPB1) scntw[i] = 0;
    __syncthreads();

    // contiguous chunk per block, multiple of ROWS_ITER (keeps int4 labels aligned)
    const int chunk = ((n + G1 * ROWS_ITER - 1) / (G1 * ROWS_ITER)) * ROWS_ITER;
    const int r0 = blockIdx.x * chunk;
    const int r1 = min(n, r0 + chunk);

    int row = r0;
    for (; row + ROWS_ITER <= r1; row += ROWS_ITER) {
        const int base = row + grp * U;

        int lab[U];
        {
            const int4* lp = (const int4*)(labels + base);
            #pragma unroll
            for (int k = 0; k < U / 4; k++) {
                int4 l4 = lp[k];
                lab[4*k+0] = l4.x; lab[4*k+1] = l4.y;
                lab[4*k+2] = l4.z; lab[4*k+3] = l4.w;
            }
        }

        // vectorized, batched loads: 16 independent LDG.64 per thread
        float2 v[U];
        #pragma unroll
        for (int u = 0; u < U; u++)
            v[u] = *(const float2*)(x + (size_t)(base + u) * D + col2);

        // exclusive column-pair ownership within the replica -> no races
        #pragma unroll
        for (int u = 0; u < U; u++) {
            float2* a = (float2*)&acc[lab[u] * D + col2];
            float2 cur = *a;
            cur.x += v[u].x;
            cur.y += v[u].y;
            *a = cur;
        }

        // counts: one lane per group counts its 16 rows into warp replica
        if (ltid == 0) {
            #pragma unroll
            for (int k = 0; k < U; k++)
                scntw[wid * C + lab[k]] += 1;
        }
    }

    // tail rows (group 0 only)
    if (grp == 0) {
        for (int m = row; m < r1; m++) {
            int lb = labels[m];
            acc[lb * D + col2]     += x[(size_t)m * D + col2];
            acc[lb * D + col2 + 1] += x[(size_t)m * D + col2 + 1];
            if (ltid == 0) scntw[lb] += 1;
        }
    }
    __syncthreads();

    // merge replicas; write to transposed scratch [C][G1][D]
    for (int i = tid; i < C * D; i += TPB1) {
        float s = 0.f;
        #pragma unroll
        for (int g = 0; g < GROUPS; g++) s += acc_all[g * C * D + i];
        int c = i >> 7, d = i & 127;
        g_partS[(size_t)c * (G1 * D) + (size_t)blockIdx.x * D + d] = s;
    }
    if (tid < C) {
        int s = 0;
        #pragma unroll
        for (int w = 0; w < 12; w++) s += scntw[w * C + tid];
        g_partCnt[blockIdx.x * C + tid] = s;
    }
}

__global__ __launch_bounds__(512)
void pass2_kernel(const float* __restrict__ W,
                  const float* __restrict__ bias,
                  float* __restrict__ out) {
    __shared__ float sW[D * E];     // 32 KB
    __shared__ float sPart[4 * D];
    __shared__ float Srow[D];
    __shared__ float sCnt;

    const int c    = blockIdx.x;
    const int tid  = threadIdx.x;
    const int part = tid >> 7;      // 4-way split of the g range
    const int d    = tid & 127;

    // contiguous, coalesced reduction of this class's 148 partials
    const float* base = g_partS + (size_t)c * (G1 * D);
    float s = 0.f;
    #pragma unroll 4
    for (int g = part; g < G1; g += 4)
        s += base[(size_t)g * D + d];
    sPart[tid] = s;

    for (int i = tid; i < D * E; i += 512) sW[i] = W[i];

    if (tid < 32) {
        int cs = 0;
        for (int g = tid; g < G1; g += 32) cs += g_partCnt[g * C + c];
        #pragma unroll
        for (int o = 16; o; o >>= 1) cs += __shfl_down_sync(0xffffffffu, cs, o);
        if (tid == 0) sCnt = (float)cs;
    }
    __syncthreads();

    if (tid < D)
        Srow[tid] = sPart[tid] + sPart[128 + tid] + sPart[256 + tid] + sPart[384 + tid];
    __syncthreads();

    if (tid < E) {
        float acc = 0.f;
        #pragma unroll
        for (int dd = 0; dd < D; dd++)
            acc += Srow[dd] * sW[dd * E + tid];
        float cnt = sCnt;
        out[c * E + tid] = (acc + cnt * bias[tid]) / fmaxf(cnt, 1.f);
    }
}

extern "C" void kernel_launch(void* const* d_in, const int* in_sizes, int n_in,
                              void* d_out, int out_size) {
    const float* x      = (const float*)d_in[0];   // [N, 128] f32
    const int*   labels = (const int*)d_in[1];     // [N] i32
    const float* W      = (const float*)d_in[2];   // [128, 64] f32
    const float* bias   = (const float*)d_in[3];   // [64] f32
    float* out = (float*)d_out;                    // [64, 64] f32

    const int n = in_sizes[1];

    const size_t smem1 = (size_t)GROUPS * C * D * sizeof(float)
                       + 12 * C * sizeof(int);     // 199,680 B
    cudaFuncSetAttribute(pass1_kernel,
                         cudaFuncAttributeMaxDynamicSharedMemorySize,
                         (int)smem1);

    pass1_kernel<<<G1, TPB1, smem1>>>(x, labels, n);
    pass2_kernel<<<C, 512>>>(W, bias, out);
}

// round 3
// speedup vs baseline: 1.4232x; 1.0058x over previous
#include <cuda_runtime.h>

constexpr int D  = 128;   // D_IN
constexpr int C  = 64;    // NUM_CLASSES
constexpr int E  = 64;    // D_OUT
constexpr int G1 = 148;   // pass-1 grid (one block per SM)
constexpr int TPB1 = 384; // 12 warps
constexpr int GROUPS = 6; // 2 warps per group, one 32KB replica each
constexpr int U = 16;     // rows per group per iteration
constexpr int ROWS_ITER = GROUPS * U;  // 96 rows / block / iter

// Scratch (allocation-free). Layout: [C][G1][D] so pass2 reads contiguously.
__device__ float g_partS[(size_t)C * G1 * D];   // ~4.85 MB
__device__ int   g_partCnt[G1 * C];

__global__ __launch_bounds__(TPB1, 1)
void pass1_kernel(const float* __restrict__ x,
                  const int* __restrict__ labels,
                  int n) {
    extern __shared__ float sm[];
    float* acc_all = sm;                               // GROUPS * C * D
    int*   scntw   = (int*)(sm + GROUPS * C * D);      // 12 warps * C

    const int tid  = threadIdx.x;
    const int grp  = tid >> 6;        // group 0..5 (2 warps each)
    const int ltid = tid & 63;        // lane within group
    const int wid  = tid >> 5;        // warp id 0..11
    const int col2 = ltid * 2;        // owned column pair
    float* acc = acc_all + grp * (C * D);

    for (int i = tid; i < GROUPS * C * D; i += TPB1) acc_all[i] = 0.f;
    for (int i = tid; i < 12 * C; i += TPB1) scntw[i] = 0;
    __syncthreads();

    // contiguous chunk per block, multiple of ROWS_ITER (keeps int4 labels aligned)
    const int chunk = ((n + G1 * ROWS_ITER - 1) / (G1 * ROWS_ITER)) * ROWS_ITER;
    const int r0 = blockIdx.x * chunk;
    const int r1 = min(n, r0 + chunk);

    int row = r0;
    for (; row + ROWS_ITER <= r1; row += ROWS_ITER) {
        const int base = row + grp * U;

        int lab[U];
        {
            const int4* lp = (const int4*)(labels + base);
            #pragma unroll
            for (int k = 0; k < U / 4; k++) {
                int4 l4 = lp[k];
                lab[4*k+0] = l4.x; lab[4*k+1] = l4.y;
                lab[4*k+2] = l4.z; lab[4*k+3] = l4.w;
            }
        }

        // vectorized, batched loads: 16 independent LDG.64 per thread
        float2 v[U];
        #pragma unroll
        for (int u = 0; u < U; u++)
            v[u] = *(const float2*)(x + (size_t)(base + u) * D + col2);

        // exclusive column-pair ownership within the replica -> no races
        #pragma unroll
        for (int u = 0; u < U; u++) {
            float2* a = (float2*)&acc[lab[u] * D + col2];
            float2 cur = *a;
            cur.x += v[u].x;
            cur.y += v[u].y;
            *a = cur;
        }

        // counts: one lane per group counts its 16 rows into warp replica
        if (ltid == 0) {
            #pragma unroll
            for (int k = 0; k < U; k++)
                scntw[wid * C + lab[k]] += 1;
        }
    }

    // tail rows (group 0 only)
    if (grp == 0) {
        for (int m = row; m < r1; m++) {
            int lb = labels[m];
            acc[lb * D + col2]     += x[(size_t)m * D + col2];
            acc[lb * D + col2 + 1] += x[(size_t)m * D + col2 + 1];
            if (ltid == 0) scntw[lb] += 1;
        }
    }
    __syncthreads();

    // merge replicas; write to transposed scratch [C][G1][D]
    for (int i = tid; i < C * D; i += TPB1) {
        float s = 0.f;
        #pragma unroll
        for (int g = 0; g < GROUPS; g++) s += acc_all[g * C * D + i];
        int c = i >> 7, d = i & 127;
        g_partS[(size_t)c * (G1 * D) + (size_t)blockIdx.x * D + d] = s;
    }
    if (tid < C) {
        int s = 0;
        #pragma unroll
        for (int w = 0; w < 12; w++) s += scntw[w * C + tid];
        g_partCnt[blockIdx.x * C + tid] = s;
    }
}

__global__ __launch_bounds__(512)
void pass2_kernel(const float* __restrict__ W,
                  const float* __restrict__ bias,
                  float* __restrict__ out) {
    __shared__ float sW[D * E];     // 32 KB
    __shared__ float sPart[4 * D];
    __shared__ float Srow[D];
    __shared__ float sCnt;

    const int c    = blockIdx.x;
    const int tid  = threadIdx.x;
    const int part = tid >> 7;      // 4-way split of the g range
    const int d    = tid & 127;

    // contiguous, coalesced reduction of this class's 148 partials
    const float* base = g_partS + (size_t)c * (G1 * D);
    float s = 0.f;
    #pragma unroll 4
    for (int g = part; g < G1; g += 4)
        s += base[(size_t)g * D + d];
    sPart[tid] = s;

    for (int i = tid; i < D * E; i += 512) sW[i] = W[i];

    if (tid < 32) {
        int cs = 0;
        for (int g = tid; g < G1; g += 32) cs += g_partCnt[g * C + c];
        #pragma unroll
        for (int o = 16; o; o >>= 1) cs += __shfl_down_sync(0xffffffffu, cs, o);
        if (tid == 0) sCnt = (float)cs;
    }
    __syncthreads();

    if (tid < D)
        Srow[tid] = sPart[tid] + sPart[128 + tid] + sPart[256 + tid] + sPart[384 + tid];
    __syncthreads();

    if (tid < E) {
        float acc = 0.f;
        #pragma unroll
        for (int dd = 0; dd < D; dd++)
            acc += Srow[dd] * sW[dd * E + tid];
        float cnt = sCnt;
        out[c * E + tid] = (acc + cnt * bias[tid]) / fmaxf(cnt, 1.f);
    }
}

extern "C" void kernel_launch(void* const* d_in, const int* in_sizes, int n_in,
                              void* d_out, int out_size) {
    const float* x      = (const float*)d_in[0];   // [N, 128] f32
    const int*   labels = (const int*)d_in[1];     // [N] i32
    const float* W      = (const float*)d_in[2];   // [128, 64] f32
    const float* bias   = (const float*)d_in[3];   // [64] f32
    float* out = (float*)d_out;                    // [64, 64] f32

    const int n = in_sizes[1];

    const size_t smem1 = (size_t)GROUPS * C * D * sizeof(float)
                       + 12 * C * sizeof(int);     // 199,680 B
    cudaFuncSetAttribute(pass1_kernel,
                         cudaFuncAttributeMaxDynamicSharedMemorySize,
                         (int)smem1);

    pass1_kernel<<<G1, TPB1, smem1>>>(x, labels, n);
    pass2_kernel<<<C, 512>>>(W, bias, out);
}